// round 12
// baseline (speedup 1.0000x reference)
#include <cuda_runtime.h>
#include <cuda_bf16.h>
#include <stdint.h>

#define NB 16
#define NN 1024
#define DD 64
#define OUT_OFF ((size_t)NB * NN * NN)

// ---------------- scratch (device globals; no allocation) ----------------
__device__ float g_rowmean[NB*NN];
__device__ float g_diag[NB*NN];
__device__ float g_r[NB*NN];            // c3*rowmean + c4*diag + p1
__device__ float g_s[NB];               // c1*mean_all + c2*mean_diag + p2
__device__ float g_pg1[NB*DD];
__device__ float g_pg2[NB*DD];
__device__ uint32_t g_Bhi[(size_t)NB*DD*NN/2];  // bf16x2-packed hi of X2_t^T [b][e][k/2]
__device__ uint32_t g_Blo[(size_t)NB*DD*NN/2];  // bf16x2-packed lo residual

// ---------------- packed fp32x2 helpers (k_node) ----------------
__device__ __forceinline__ void fma2(unsigned long long &d,
                                     unsigned long long a,
                                     unsigned long long b) {
    asm("fma.rn.f32x2 %0, %1, %2, %0;" : "+l"(d) : "l"(a), "l"(b));
}
__device__ __forceinline__ float psum(unsigned long long v) {
    return __uint_as_float((unsigned)v) + __uint_as_float((unsigned)(v >> 32));
}

// ---------------- bf16 split helpers ----------------
__device__ __forceinline__ uint32_t prmt7632(uint32_t a, uint32_t b) {
    uint32_t d;
    asm("prmt.b32 %0, %1, %2, 0x7632;" : "=r"(d) : "r"(a), "r"(b));
    return d;
}

// ---------------- m16n8k16 bf16 mma (HMMA, baseline PTX) ----------------
__device__ __forceinline__ void mma16(float* c, const uint32_t* a,
                                      uint32_t b0, uint32_t b1) {
    asm("mma.sync.aligned.m16n8k16.row.col.f32.bf16.bf16.f32 "
        "{%0,%1,%2,%3}, {%4,%5,%6,%7}, {%8,%9}, {%0,%1,%2,%3};"
        : "+f"(c[0]), "+f"(c[1]), "+f"(c[2]), "+f"(c[3])
        : "r"(a[0]), "r"(a[1]), "r"(a[2]), "r"(a[3]), "r"(b0), "r"(b1));
}

// ---------------- kernel 1: per-row stats (rowmean, diag, r) -------------
__global__ __launch_bounds__(256) void k_row_stats(
    const float* __restrict__ A, const float* __restrict__ X,
    const float* __restrict__ coeffs, const float* __restrict__ wA1)
{
    int gw = blockIdx.x * 8 + (threadIdx.x >> 5);   // global row 0..16383
    int lane = threadIdx.x & 31;
    const float4* arow = reinterpret_cast<const float4*>(A) + (size_t)gw * (NN/4);
    float s = 0.f;
#pragma unroll
    for (int w = 0; w < 8; ++w) {
        float4 v = arow[lane + (w << 5)];
        s += (v.x + v.y) + (v.z + v.w);
    }
    const float* xrow = X + (size_t)gw * DD;
    float p = xrow[lane] * wA1[lane] + xrow[lane+32] * wA1[lane+32];
#pragma unroll
    for (int o = 16; o; o >>= 1) {
        s += __shfl_xor_sync(0xffffffffu, s, o);
        p += __shfl_xor_sync(0xffffffffu, p, o);
    }
    if (lane == 0) {
        int i = gw & (NN-1);
        float d = A[(size_t)gw*NN + i];
        float rm = s * (1.f/NN);
        g_rowmean[gw] = rm;
        g_diag[gw]    = d;
        g_r[gw]       = coeffs[3]*rm + coeffs[4]*d + p;
    }
}

// ---------------- kernel 2: per-batch stats (s, pg1, pg2) ----------------
__global__ __launch_bounds__(256) void k_batch_stats(
    const float* __restrict__ X, const float* __restrict__ coeffs,
    const float* __restrict__ wA2,
    const float* __restrict__ w12, const float* __restrict__ w15, const float* __restrict__ w16,
    const float* __restrict__ w22, const float* __restrict__ w25, const float* __restrict__ w26)
{
    int b = blockIdx.x, t = threadIdx.x;
    __shared__ float red[256];
    __shared__ float sm_meanX[DD];
    __shared__ float sm_mall, sm_mdiag;

    float v1 = 0.f, v2 = 0.f;
    for (int i = t; i < NN; i += 256) { v1 += g_rowmean[b*NN+i]; v2 += g_diag[b*NN+i]; }
    red[t] = v1; __syncthreads();
    for (int o = 128; o > 0; o >>= 1) { if (t < o) red[t] += red[t+o]; __syncthreads(); }
    if (t == 0) sm_mall = red[0]*(1.f/NN);
    __syncthreads();
    red[t] = v2; __syncthreads();
    for (int o = 128; o > 0; o >>= 1) { if (t < o) red[t] += red[t+o]; __syncthreads(); }
    if (t == 0) sm_mdiag = red[0]*(1.f/NN);
    __syncthreads();

    int d = t & 63, g = t >> 6;
    float xs = 0.f;
    for (int j = g; j < NN; j += 4) xs += X[((size_t)b*NN + j)*DD + d];
    red[t] = xs; __syncthreads();
    if (g == 0) sm_meanX[d] = (red[d] + red[d+64] + red[d+128] + red[d+192]) * (1.f/NN);
    __syncthreads();

    float mall = sm_mall, mdiag = sm_mdiag;
    if (t == 0) {
        float p2 = 0.f;
        for (int k = 0; k < DD; ++k) p2 += sm_meanX[k]*wA2[k];
        g_s[b] = coeffs[1]*mall + coeffs[2]*mdiag + p2;
    } else if (t >= 64 && t < 128) {
        int e = t - 64;
        float a = 0.f;
        for (int k = 0; k < DD; ++k) a += sm_meanX[k]*w12[e*DD+k];
        g_pg1[b*DD+e] = a + mdiag*w15[e] + mall*w16[e];
    } else if (t >= 128 && t < 192) {
        int e = t - 128;
        float a = 0.f;
        for (int k = 0; k < DD; ++k) a += sm_meanX[k]*w22[e*DD+k];
        g_pg2[b*DD+e] = a + mdiag*w25[e] + mall*w26[e];
    }
}

// ---------------- kernel 3: node transforms X1_t, X2_t^T (bf16 hi/lo) ----
// dynamic smem: Xs[128*64] | W1[64*68] | W2[64*68]  (67584 B)
__global__ __launch_bounds__(256) void k_node(
    const float* __restrict__ X,
    const float* __restrict__ w11, const float* __restrict__ w13, const float* __restrict__ w14,
    const float* __restrict__ w21, const float* __restrict__ w23, const float* __restrict__ w24,
    float* __restrict__ x1o)
{
    extern __shared__ __align__(16) float sm[];
    float* Xs = sm;               // [128][64]
    float* W1 = sm + 128*DD;      // [64][68]
    float* W2 = W1 + 64*68;       // [64][68]

    const int b = blockIdx.y;
    const int it0 = blockIdx.x << 7;    // 128 rows per block
    const int tid = threadIdx.x;
    const int c4 = tid & 15, r0 = tid >> 4;   // r0 0..15
    const int ci = c4 << 2;

    const float* Xb = X + ((size_t)b*NN + it0)*DD;
#pragma unroll
    for (int t = 0; t < 8; ++t) {
        int row = r0 + (t << 4);
        *reinterpret_cast<float4*>(Xs + row*DD + ci) =
            *reinterpret_cast<const float4*>(Xb + (size_t)row*DD + ci);
    }
#pragma unroll
    for (int t = 0; t < 4; ++t) {
        int e = r0 + (t << 4);
        *reinterpret_cast<float4*>(W1 + e*68 + ci) = *reinterpret_cast<const float4*>(w11 + e*DD + ci);
        *reinterpret_cast<float4*>(W2 + e*68 + ci) = *reinterpret_cast<const float4*>(w21 + e*DD + ci);
    }
    __syncthreads();

    const int tx = tid & 15, ty = tid >> 4;
    const int e0 = tx << 2, i0 = ty << 3;   // i0 0..120

    float rmv[8], dgv[8];
#pragma unroll
    for (int r = 0; r < 8; ++r) {
        int row = b*NN + it0 + i0 + r;
        rmv[r] = g_rowmean[row];
        dgv[r] = g_diag[row];
    }

    unsigned long long acc[8][4];

    // ---- pass 1: X1_t -> x1o ----
#pragma unroll
    for (int r = 0; r < 8; ++r)
#pragma unroll
        for (int q = 0; q < 4; ++q) acc[r][q] = 0ull;
#pragma unroll 2
    for (int d = 0; d < DD; d += 4) {
        ulonglong2 a[8];
#pragma unroll
        for (int r = 0; r < 8; ++r)
            a[r] = *reinterpret_cast<const ulonglong2*>(Xs + (i0+r)*DD + d);
#pragma unroll
        for (int q = 0; q < 4; ++q) {
            ulonglong2 bv = *reinterpret_cast<const ulonglong2*>(W1 + (e0+q)*68 + d);
#pragma unroll
            for (int r = 0; r < 8; ++r) { fma2(acc[r][q], a[r].x, bv.x); fma2(acc[r][q], a[r].y, bv.y); }
        }
    }
    {
        float4 wc = *reinterpret_cast<const float4*>(w13 + e0);
        float4 wd = *reinterpret_cast<const float4*>(w14 + e0);
        float4 pg = *reinterpret_cast<const float4*>(g_pg1 + b*DD + e0);
#pragma unroll
        for (int r = 0; r < 8; ++r) {
            float4 o;
            o.x = psum(acc[r][0]) + rmv[r]*wc.x + dgv[r]*wd.x + pg.x;
            o.y = psum(acc[r][1]) + rmv[r]*wc.y + dgv[r]*wd.y + pg.y;
            o.z = psum(acc[r][2]) + rmv[r]*wc.z + dgv[r]*wd.z + pg.z;
            o.w = psum(acc[r][3]) + rmv[r]*wc.w + dgv[r]*wd.w + pg.w;
            *reinterpret_cast<float4*>(x1o + ((size_t)b*NN + it0 + i0 + r)*DD + e0) = o;
        }
    }

    // ---- pass 2: X2_t -> registers, then SMEM-bounce transpose ----
#pragma unroll
    for (int r = 0; r < 8; ++r)
#pragma unroll
        for (int q = 0; q < 4; ++q) acc[r][q] = 0ull;
#pragma unroll 2
    for (int d = 0; d < DD; d += 4) {
        ulonglong2 a[8];
#pragma unroll
        for (int r = 0; r < 8; ++r)
            a[r] = *reinterpret_cast<const ulonglong2*>(Xs + (i0+r)*DD + d);
#pragma unroll
        for (int q = 0; q < 4; ++q) {
            ulonglong2 bv = *reinterpret_cast<const ulonglong2*>(W2 + (e0+q)*68 + d);
#pragma unroll
            for (int r = 0; r < 8; ++r) { fma2(acc[r][q], a[r].x, bv.x); fma2(acc[r][q], a[r].y, bv.y); }
        }
    }
    float4 o2v[8];
    {
        float4 wc = *reinterpret_cast<const float4*>(w23 + e0);
        float4 wd = *reinterpret_cast<const float4*>(w24 + e0);
        float4 pg = *reinterpret_cast<const float4*>(g_pg2 + b*DD + e0);
#pragma unroll
        for (int r = 0; r < 8; ++r) {
            o2v[r].x = psum(acc[r][0]) + rmv[r]*wc.x + dgv[r]*wd.x + pg.x;
            o2v[r].y = psum(acc[r][1]) + rmv[r]*wc.y + dgv[r]*wd.y + pg.y;
            o2v[r].z = psum(acc[r][2]) + rmv[r]*wc.z + dgv[r]*wd.z + pg.z;
            o2v[r].w = psum(acc[r][3]) + rmv[r]*wc.w + dgv[r]*wd.w + pg.w;
        }
    }
    __syncthreads();   // all reads of Xs done -> reuse as transpose buffer
#pragma unroll
    for (int r = 0; r < 8; ++r)
        *reinterpret_cast<float4*>(Xs + (i0+r)*DD + e0) = o2v[r];
    __syncthreads();

    // transposed bf16 hi/lo packed write: g_Bhi/g_Blo [b][e][k/2]
    const int e = tid & 63, rc = tid >> 6;   // rc 0..3
#pragma unroll
    for (int rr = 0; rr < 8; ++rr) {
        int rowl = (rc << 5) + (rr << 2);
        float v0 = Xs[(rowl+0)*DD + e], v1 = Xs[(rowl+1)*DD + e];
        float v2 = Xs[(rowl+2)*DD + e], v3 = Xs[(rowl+3)*DD + e];
        uint32_t b0 = __float_as_uint(v0), b1 = __float_as_uint(v1);
        uint32_t b2 = __float_as_uint(v2), b3 = __float_as_uint(v3);
        float l0 = v0 - __uint_as_float(b0 & 0xffff0000u);
        float l1 = v1 - __uint_as_float(b1 & 0xffff0000u);
        float l2 = v2 - __uint_as_float(b2 & 0xffff0000u);
        float l3 = v3 - __uint_as_float(b3 & 0xffff0000u);
        uint2 hp, lp;
        hp.x = prmt7632(b0, b1); hp.y = prmt7632(b2, b3);
        lp.x = prmt7632(__float_as_uint(l0), __float_as_uint(l1));
        lp.y = prmt7632(__float_as_uint(l2), __float_as_uint(l3));
        size_t off = (((size_t)b*DD + e)*NN + it0 + rowl) >> 1;
        *reinterpret_cast<uint2*>(g_Bhi + off) = hp;
        *reinterpret_cast<uint2*>(g_Blo + off) = lp;
    }
}

// ---------------- kernel 4: bf16x3 HMMA GEMM (full-K, no split) ----------
// 256 threads, 64x64 tile, KC=32, double-buffered 40KB smem -> 2 CTAs/SM,
// grid 16x16 = 256 blocks (single wave). Epilogue folds acc/1024 + X1_t
// directly into x1o (no partials, no fix kernel).
#define STG_U (4*64*20)   // 5120 u32 per stage (20 KB): Ahi|Alo|Bhi|Blo
__global__ __launch_bounds__(256, 2) void k_gemm(
    const float* __restrict__ A, const float* __restrict__ coeffs,
    float* __restrict__ At, float* __restrict__ x1o)
{
    extern __shared__ __align__(16) uint32_t smu[];
    const int tid = threadIdx.x;
    const int wid = tid >> 5, lane = tid & 31;
    const int b = blockIdx.y, it0 = blockIdx.x << 6;   // 64 rows per block

    // loader coords (KC=32)
    const int rb = tid >> 3;            // 0..31 (A rows rb, rb+32)
    const int ci = (tid & 7) << 2;      // 0..28 (k floats)
    const int eb = tid >> 2;            // 0..63 (B row)
    const int uc = (tid & 3) << 2;      // 0,4,8,12 (u32 cols)

    const float c0 = coeffs[0];
    const float sbv = g_s[b];
    float rloc[2];
#pragma unroll
    for (int i = 0; i < 2; ++i) rloc[i] = sbv + g_r[b*NN + it0 + rb + (i << 5)];

    const float* Ab = A  + ((size_t)b*NN + it0)*NN;
    float*       Ob = At + ((size_t)b*NN + it0)*NN;
    const uint32_t* Bhg = g_Bhi + (size_t)b*DD*(NN/2);
    const uint32_t* Blg = g_Blo + (size_t)b*DD*(NN/2);

    float acc[4][4];
#pragma unroll
    for (int nt = 0; nt < 4; ++nt)
#pragma unroll
        for (int q = 0; q < 4; ++q) acc[nt][q] = 0.f;

    float4 Ar[2], rjv;
    uint4 Bh4, Bl4;
    auto fetch = [&](int s) {
        const int k0 = s << 5;
        rjv = *reinterpret_cast<const float4*>(g_r + b*NN + k0 + ci);
#pragma unroll
        for (int i = 0; i < 2; ++i)
            Ar[i] = *reinterpret_cast<const float4*>(Ab + (size_t)(rb + (i << 5))*NN + k0 + ci);
        const int k0u = k0 >> 1;
        Bh4 = *reinterpret_cast<const uint4*>(Bhg + (size_t)eb*(NN/2) + k0u + uc);
        Bl4 = *reinterpret_cast<const uint4*>(Blg + (size_t)eb*(NN/2) + k0u + uc);
    };
    auto fill = [&](int s, int buf) {
        const int k0 = s << 5;
        uint32_t* Ahi = smu + buf * STG_U;
        uint32_t* Alo = Ahi + 64*20;
        uint32_t* Bhi = Alo + 64*20;
        uint32_t* Blo = Bhi + 64*20;
#pragma unroll
        for (int i = 0; i < 2; ++i) {
            int row = rb + (i << 5);
            float4 atv;
            atv.x = fmaf(c0, Ar[i].x, rloc[i] + rjv.x);
            atv.y = fmaf(c0, Ar[i].y, rloc[i] + rjv.y);
            atv.z = fmaf(c0, Ar[i].z, rloc[i] + rjv.z);
            atv.w = fmaf(c0, Ar[i].w, rloc[i] + rjv.w);
            *reinterpret_cast<float4*>(Ob + (size_t)row*NN + k0 + ci) = atv;   // A_t out
            uint32_t bx = __float_as_uint(atv.x), by = __float_as_uint(atv.y);
            uint32_t bz = __float_as_uint(atv.z), bw = __float_as_uint(atv.w);
            float lx = atv.x - __uint_as_float(bx & 0xffff0000u);
            float ly = atv.y - __uint_as_float(by & 0xffff0000u);
            float lz = atv.z - __uint_as_float(bz & 0xffff0000u);
            float lw = atv.w - __uint_as_float(bw & 0xffff0000u);
            uint2 hp, lp;
            hp.x = prmt7632(bx, by); hp.y = prmt7632(bz, bw);
            lp.x = prmt7632(__float_as_uint(lx), __float_as_uint(ly));
            lp.y = prmt7632(__float_as_uint(lz), __float_as_uint(lw));
            *reinterpret_cast<uint2*>(Ahi + row*20 + (ci >> 1)) = hp;
            *reinterpret_cast<uint2*>(Alo + row*20 + (ci >> 1)) = lp;
        }
        *reinterpret_cast<uint4*>(Bhi + eb*20 + uc) = Bh4;
        *reinterpret_cast<uint4*>(Blo + eb*20 + uc) = Bl4;
    };

    const int g = lane >> 2, t = lane & 3;
    const int m0 = (wid & 3) << 4;       // 4 m-groups of 16 rows
    const int e0 = (wid >> 2) << 5;      // 2 e-groups of 32 cols

    fetch(0);
    fill(0, 0);
    __syncthreads();

    for (int s = 0; s < 32; ++s) {
        if (s < 31) fetch(s + 1);        // LDG in flight behind MMAs
        const uint32_t* Ahi = smu + (s & 1) * STG_U;
        const uint32_t* Alo = Ahi + 64*20;
        const uint32_t* Bhi = Alo + 64*20;
        const uint32_t* Blo = Bhi + 64*20;
#pragma unroll
        for (int ks = 0; ks < 2; ++ks) {
            const int kk2 = ks << 3;     // u32 offset (k16 step = 8 u32)
            uint32_t ah[4], al[4];
            ah[0] = Ahi[(m0+g  )*20 + kk2 + t];
            ah[1] = Ahi[(m0+g+8)*20 + kk2 + t];
            ah[2] = Ahi[(m0+g  )*20 + kk2 + 4 + t];
            ah[3] = Ahi[(m0+g+8)*20 + kk2 + 4 + t];
            al[0] = Alo[(m0+g  )*20 + kk2 + t];
            al[1] = Alo[(m0+g+8)*20 + kk2 + t];
            al[2] = Alo[(m0+g  )*20 + kk2 + 4 + t];
            al[3] = Alo[(m0+g+8)*20 + kk2 + 4 + t];
            uint32_t bh[4][2], bl[4][2];
#pragma unroll
            for (int nt = 0; nt < 4; ++nt) {
                const int er = (e0 + (nt << 3) + g)*20 + kk2 + t;
                bh[nt][0] = Bhi[er]; bh[nt][1] = Bhi[er + 4];
                bl[nt][0] = Blo[er]; bl[nt][1] = Blo[er + 4];
            }
#pragma unroll
            for (int nt = 0; nt < 4; ++nt)
                mma16(acc[nt], ah, bh[nt][0], bh[nt][1]);
#pragma unroll
            for (int nt = 0; nt < 4; ++nt)
                mma16(acc[nt], ah, bl[nt][0], bl[nt][1]);
#pragma unroll
            for (int nt = 0; nt < 4; ++nt)
                mma16(acc[nt], al, bh[nt][0], bh[nt][1]);
        }
        if (s < 31) {
            fill(s + 1, (s + 1) & 1);    // writes the other buffer
            __syncthreads();
        }
    }

    // ---- epilogue: out = acc/1024 + X1_t (in place in x1o) ----
    const float inv = 1.0f / 1024.0f;
    const int row1 = it0 + m0 + g;
    const size_t b1 = ((size_t)b*NN + row1)*DD;
    const size_t b2 = b1 + 8*DD;
#pragma unroll
    for (int nt = 0; nt < 4; ++nt) {
        const int col = e0 + (nt << 3) + (t << 1);
        float2 x1 = *reinterpret_cast<const float2*>(x1o + b1 + col);
        float2 o1;
        o1.x = acc[nt][0]*inv + x1.x;
        o1.y = acc[nt][1]*inv + x1.y;
        *reinterpret_cast<float2*>(x1o + b1 + col) = o1;
        float2 x2 = *reinterpret_cast<const float2*>(x1o + b2 + col);
        float2 o2;
        o2.x = acc[nt][2]*inv + x2.x;
        o2.y = acc[nt][3]*inv + x2.y;
        *reinterpret_cast<float2*>(x1o + b2 + col) = o2;
    }
}

// ---------------- launch ----------------
extern "C" void kernel_launch(void* const* d_in, const int* in_sizes, int n_in,
                              void* d_out, int out_size)
{
    const float* A      = (const float*)d_in[0];
    const float* X      = (const float*)d_in[1];
    const float* coeffs = (const float*)d_in[2];
    const float* wA1    = (const float*)d_in[3];
    const float* wA2    = (const float*)d_in[4];
    const float* w11    = (const float*)d_in[5];
    const float* w12    = (const float*)d_in[6];
    const float* w13    = (const float*)d_in[7];
    const float* w14    = (const float*)d_in[8];
    const float* w15    = (const float*)d_in[9];
    const float* w16    = (const float*)d_in[10];
    const float* w21    = (const float*)d_in[11];
    const float* w22    = (const float*)d_in[12];
    const float* w23    = (const float*)d_in[13];
    const float* w24    = (const float*)d_in[14];
    const float* w25    = (const float*)d_in[15];
    const float* w26    = (const float*)d_in[16];

    float* out = (float*)d_out;
    float* x1o = out + OUT_OFF;

    const int NODE_SMEM = (128*DD + 2*64*68) * (int)sizeof(float);  // 67584
    cudaFuncSetAttribute(k_node, cudaFuncAttributeMaxDynamicSharedMemorySize, NODE_SMEM);
    const int GEMM_SMEM = 2 * STG_U * (int)sizeof(uint32_t);        // 40960
    cudaFuncSetAttribute(k_gemm, cudaFuncAttributeMaxDynamicSharedMemorySize, GEMM_SMEM);

    k_row_stats  <<<2048, 256>>>(A, X, coeffs, wA1);
    k_batch_stats<<<16,   256>>>(X, coeffs, wA2, w12, w15, w16, w22, w25, w26);
    k_node       <<<dim3(8,16), 256, NODE_SMEM>>>(X, w11, w13, w14, w21, w23, w24, x1o);
    k_gemm       <<<dim3(16,16), 256, GEMM_SMEM>>>(A, coeffs, out, x1o);
}

// round 13
// speedup vs baseline: 1.1153x; 1.1153x over previous
#include <cuda_runtime.h>
#include <cuda_bf16.h>
#include <stdint.h>

#define NB 16
#define NN 1024
#define DD 64
#define OUT_OFF ((size_t)NB * NN * NN)

// ---------------- scratch (device globals; no allocation) ----------------
__device__ float g_rowmean[NB*NN];
__device__ float g_diag[NB*NN];
__device__ float g_r[NB*NN];            // c3*rowmean + c4*diag + p1
__device__ float g_s[NB];               // c1*mean_all + c2*mean_diag + p2
__device__ float g_pg1[NB*DD];
__device__ float g_pg2[NB*DD];
__device__ float g_meanX[NB*DD];
__device__ float g_T2[(size_t)NB*NN*DD];        // raw X@W2^T
__device__ uint32_t g_Bhi[(size_t)NB*DD*NN/2];  // bf16x2-packed hi of X2_t^T [b][e][k/2]
__device__ uint32_t g_Blo[(size_t)NB*DD*NN/2];  // bf16x2-packed lo residual
__device__ float g_part0[(size_t)NB*NN*DD];     // split-K partial (kv=0)
__device__ float g_part1[(size_t)NB*NN*DD];     // split-K partial (kv=1)

// ---------------- packed fp32x2 helpers ----------------
__device__ __forceinline__ void fma2(unsigned long long &d,
                                     unsigned long long a,
                                     unsigned long long b) {
    asm("fma.rn.f32x2 %0, %1, %2, %0;" : "+l"(d) : "l"(a), "l"(b));
}
__device__ __forceinline__ float psum(unsigned long long v) {
    return __uint_as_float((unsigned)v) + __uint_as_float((unsigned)(v >> 32));
}

// ---------------- bf16 split helpers ----------------
__device__ __forceinline__ uint32_t prmt7632(uint32_t a, uint32_t b) {
    uint32_t d;
    asm("prmt.b32 %0, %1, %2, 0x7632;" : "=r"(d) : "r"(a), "r"(b));
    return d;
}

// ---------------- m16n8k16 bf16 mma (HMMA, baseline PTX) ----------------
__device__ __forceinline__ void mma16(float* c, const uint32_t* a,
                                      uint32_t b0, uint32_t b1) {
    asm("mma.sync.aligned.m16n8k16.row.col.f32.bf16.bf16.f32 "
        "{%0,%1,%2,%3}, {%4,%5,%6,%7}, {%8,%9}, {%0,%1,%2,%3};"
        : "+f"(c[0]), "+f"(c[1]), "+f"(c[2]), "+f"(c[3])
        : "r"(a[0]), "r"(a[1]), "r"(a[2]), "r"(a[3]), "r"(b0), "r"(b1));
}

// ============ kernel 1 (fused front): blocks 0-127 -> X@W GEMMs,
// blocks 128-143 -> meanX, blocks 144-2191 -> row stats. All independent.
__global__ __launch_bounds__(256) void k_front(
    const float* __restrict__ A, const float* __restrict__ X,
    const float* __restrict__ coeffs, const float* __restrict__ wA1,
    const float* __restrict__ w11, const float* __restrict__ w21,
    float* __restrict__ x1o)
{
    const int bid = blockIdx.x;
    const int tid = threadIdx.x;

    if (bid < 128) {
        // ---- X@W1^T -> x1o (raw), X@W2^T -> g_T2 (raw) ----
        extern __shared__ __align__(16) float sm[];
        float* Xs = sm;               // [128][64]
        float* W1 = sm + 128*DD;      // [64][68]
        float* W2 = W1 + 64*68;       // [64][68]

        const int b = bid >> 3;
        const int it0 = (bid & 7) << 7;
        const int c4 = tid & 15, r0 = tid >> 4;
        const int ci = c4 << 2;

        const float* Xb = X + ((size_t)b*NN + it0)*DD;
#pragma unroll
        for (int t = 0; t < 8; ++t) {
            int row = r0 + (t << 4);
            *reinterpret_cast<float4*>(Xs + row*DD + ci) =
                *reinterpret_cast<const float4*>(Xb + (size_t)row*DD + ci);
        }
#pragma unroll
        for (int t = 0; t < 4; ++t) {
            int e = r0 + (t << 4);
            *reinterpret_cast<float4*>(W1 + e*68 + ci) = *reinterpret_cast<const float4*>(w11 + e*DD + ci);
            *reinterpret_cast<float4*>(W2 + e*68 + ci) = *reinterpret_cast<const float4*>(w21 + e*DD + ci);
        }
        __syncthreads();

        const int tx = tid & 15, ty = tid >> 4;
        const int e0 = tx << 2, i0 = ty << 3;

        unsigned long long acc[8][4];
        // pass 1: X@W1^T
#pragma unroll
        for (int r = 0; r < 8; ++r)
#pragma unroll
            for (int q = 0; q < 4; ++q) acc[r][q] = 0ull;
#pragma unroll 2
        for (int d = 0; d < DD; d += 4) {
            ulonglong2 a[8];
#pragma unroll
            for (int r = 0; r < 8; ++r)
                a[r] = *reinterpret_cast<const ulonglong2*>(Xs + (i0+r)*DD + d);
#pragma unroll
            for (int q = 0; q < 4; ++q) {
                ulonglong2 bv = *reinterpret_cast<const ulonglong2*>(W1 + (e0+q)*68 + d);
#pragma unroll
                for (int r = 0; r < 8; ++r) { fma2(acc[r][q], a[r].x, bv.x); fma2(acc[r][q], a[r].y, bv.y); }
            }
        }
#pragma unroll
        for (int r = 0; r < 8; ++r) {
            float4 o;
            o.x = psum(acc[r][0]); o.y = psum(acc[r][1]);
            o.z = psum(acc[r][2]); o.w = psum(acc[r][3]);
            *reinterpret_cast<float4*>(x1o + ((size_t)b*NN + it0 + i0 + r)*DD + e0) = o;
        }
        // pass 2: X@W2^T
#pragma unroll
        for (int r = 0; r < 8; ++r)
#pragma unroll
            for (int q = 0; q < 4; ++q) acc[r][q] = 0ull;
#pragma unroll 2
        for (int d = 0; d < DD; d += 4) {
            ulonglong2 a[8];
#pragma unroll
            for (int r = 0; r < 8; ++r)
                a[r] = *reinterpret_cast<const ulonglong2*>(Xs + (i0+r)*DD + d);
#pragma unroll
            for (int q = 0; q < 4; ++q) {
                ulonglong2 bv = *reinterpret_cast<const ulonglong2*>(W2 + (e0+q)*68 + d);
#pragma unroll
                for (int r = 0; r < 8; ++r) { fma2(acc[r][q], a[r].x, bv.x); fma2(acc[r][q], a[r].y, bv.y); }
            }
        }
#pragma unroll
        for (int r = 0; r < 8; ++r) {
            float4 o;
            o.x = psum(acc[r][0]); o.y = psum(acc[r][1]);
            o.z = psum(acc[r][2]); o.w = psum(acc[r][3]);
            *reinterpret_cast<float4*>(g_T2 + ((size_t)b*NN + it0 + i0 + r)*DD + e0) = o;
        }
    } else if (bid < 144) {
        // ---- meanX for batch b ----
        __shared__ float red[256];
        const int b = bid - 128;
        const int d = tid & 63, g = tid >> 6;
        float xs = 0.f;
        for (int j = g; j < NN; j += 4) xs += X[((size_t)b*NN + j)*DD + d];
        red[tid] = xs; __syncthreads();
        if (g == 0)
            g_meanX[b*DD + d] = (red[d] + red[d+64] + red[d+128] + red[d+192]) * (1.f/NN);
    } else {
        // ---- per-row stats: rowmean, diag, r ----
        int gw = (bid - 144) * 8 + (tid >> 5);
        int lane = tid & 31;
        const float4* arow = reinterpret_cast<const float4*>(A) + (size_t)gw * (NN/4);
        float s = 0.f;
#pragma unroll
        for (int w = 0; w < 8; ++w) {
            float4 v = arow[lane + (w << 5)];
            s += (v.x + v.y) + (v.z + v.w);
        }
        const float* xrow = X + (size_t)gw * DD;
        float p = xrow[lane] * wA1[lane] + xrow[lane+32] * wA1[lane+32];
#pragma unroll
        for (int o = 16; o; o >>= 1) {
            s += __shfl_xor_sync(0xffffffffu, s, o);
            p += __shfl_xor_sync(0xffffffffu, p, o);
        }
        if (lane == 0) {
            int i = gw & (NN-1);
            float d = A[(size_t)gw*NN + i];
            float rm = s * (1.f/NN);
            g_rowmean[gw] = rm;
            g_diag[gw]    = d;
            g_r[gw]       = coeffs[3]*rm + coeffs[4]*d + p;
        }
    }
}

// ============ kernel 2: per-batch scalars (s, pg1, pg2) ============
__global__ __launch_bounds__(256) void k_batch_finish(
    const float* __restrict__ coeffs, const float* __restrict__ wA2,
    const float* __restrict__ w12, const float* __restrict__ w15, const float* __restrict__ w16,
    const float* __restrict__ w22, const float* __restrict__ w25, const float* __restrict__ w26)
{
    int b = blockIdx.x, t = threadIdx.x;
    __shared__ float red[256];
    __shared__ float smX[DD];
    __shared__ float sm_mall, sm_mdiag;

    float v1 = 0.f, v2 = 0.f;
    for (int i = t; i < NN; i += 256) { v1 += g_rowmean[b*NN+i]; v2 += g_diag[b*NN+i]; }
    red[t] = v1; __syncthreads();
    for (int o = 128; o > 0; o >>= 1) { if (t < o) red[t] += red[t+o]; __syncthreads(); }
    if (t == 0) sm_mall = red[0]*(1.f/NN);
    __syncthreads();
    red[t] = v2; __syncthreads();
    for (int o = 128; o > 0; o >>= 1) { if (t < o) red[t] += red[t+o]; __syncthreads(); }
    if (t == 0) sm_mdiag = red[0]*(1.f/NN);
    if (t < DD) smX[t] = g_meanX[b*DD + t];
    __syncthreads();

    float mall = sm_mall, mdiag = sm_mdiag;
    if (t == 0) {
        float p2 = 0.f;
        for (int k = 0; k < DD; ++k) p2 += smX[k]*wA2[k];
        g_s[b] = coeffs[1]*mall + coeffs[2]*mdiag + p2;
    } else if (t >= 64 && t < 128) {
        int e = t - 64;
        float a = 0.f;
        for (int k = 0; k < DD; ++k) a += smX[k]*w12[e*DD+k];
        g_pg1[b*DD+e] = a + mdiag*w15[e] + mall*w16[e];
    } else if (t >= 128 && t < 192) {
        int e = t - 128;
        float a = 0.f;
        for (int k = 0; k < DD; ++k) a += smX[k]*w22[e*DD+k];
        g_pg2[b*DD+e] = a + mdiag*w25[e] + mall*w26[e];
    }
}

// ============ kernel 3: finish node transforms ============
// x1o += rank-1 terms + pg1; X2_t = T2 + rank-1 + pg2 -> bf16 hi/lo transpose.
__global__ __launch_bounds__(256) void k_finish(
    const float* __restrict__ w13, const float* __restrict__ w14,
    const float* __restrict__ w23, const float* __restrict__ w24,
    float* __restrict__ x1o)
{
    __shared__ __align__(16) float Xs[128*DD];
    const int b = blockIdx.y;
    const int it0 = blockIdx.x << 7;
    const int tid = threadIdx.x;
    const int tx = tid & 15, ty = tid >> 4;
    const int e0 = tx << 2, i0 = ty << 3;

    float4 wc1 = *reinterpret_cast<const float4*>(w13 + e0);
    float4 wd1 = *reinterpret_cast<const float4*>(w14 + e0);
    float4 pg1 = *reinterpret_cast<const float4*>(g_pg1 + b*DD + e0);
    float4 wc2 = *reinterpret_cast<const float4*>(w23 + e0);
    float4 wd2 = *reinterpret_cast<const float4*>(w24 + e0);
    float4 pg2 = *reinterpret_cast<const float4*>(g_pg2 + b*DD + e0);

#pragma unroll
    for (int r = 0; r < 8; ++r) {
        int gidx = b*NN + it0 + i0 + r;
        float rm = g_rowmean[gidx], dg = g_diag[gidx];
        size_t off = (size_t)gidx*DD + e0;
        float4 t1 = *reinterpret_cast<const float4*>(x1o + off);
        t1.x += rm*wc1.x + dg*wd1.x + pg1.x;
        t1.y += rm*wc1.y + dg*wd1.y + pg1.y;
        t1.z += rm*wc1.z + dg*wd1.z + pg1.z;
        t1.w += rm*wc1.w + dg*wd1.w + pg1.w;
        *reinterpret_cast<float4*>(x1o + off) = t1;
        float4 t2 = *reinterpret_cast<const float4*>(g_T2 + off);
        float4 o2;
        o2.x = t2.x + rm*wc2.x + dg*wd2.x + pg2.x;
        o2.y = t2.y + rm*wc2.y + dg*wd2.y + pg2.y;
        o2.z = t2.z + rm*wc2.z + dg*wd2.z + pg2.z;
        o2.w = t2.w + rm*wc2.w + dg*wd2.w + pg2.w;
        *reinterpret_cast<float4*>(Xs + (i0+r)*DD + e0) = o2;
    }
    __syncthreads();

    // transposed bf16 hi/lo packed write: g_Bhi/g_Blo [b][e][k/2]
    const int e = tid & 63, rc = tid >> 6;
#pragma unroll
    for (int rr = 0; rr < 8; ++rr) {
        int rowl = (rc << 5) + (rr << 2);
        float v0 = Xs[(rowl+0)*DD + e], v1 = Xs[(rowl+1)*DD + e];
        float v2 = Xs[(rowl+2)*DD + e], v3 = Xs[(rowl+3)*DD + e];
        uint32_t b0 = __float_as_uint(v0), b1 = __float_as_uint(v1);
        uint32_t b2 = __float_as_uint(v2), b3 = __float_as_uint(v3);
        float l0 = v0 - __uint_as_float(b0 & 0xffff0000u);
        float l1 = v1 - __uint_as_float(b1 & 0xffff0000u);
        float l2 = v2 - __uint_as_float(b2 & 0xffff0000u);
        float l3 = v3 - __uint_as_float(b3 & 0xffff0000u);
        uint2 hp, lp;
        hp.x = prmt7632(b0, b1); hp.y = prmt7632(b2, b3);
        lp.x = prmt7632(__float_as_uint(l0), __float_as_uint(l1));
        lp.y = prmt7632(__float_as_uint(l2), __float_as_uint(l3));
        size_t off = (((size_t)b*DD + e)*NN + it0 + rowl) >> 1;
        *reinterpret_cast<uint2*>(g_Bhi + off) = hp;
        *reinterpret_cast<uint2*>(g_Blo + off) = lp;
    }
}

// ============ kernel 4: bf16x3 HMMA GEMM (split-K=2) — R11 verbatim ======
#define STG_U (2*128*20 + 2*64*20)   // 7680 u32 per stage (30 KB)
__global__ __launch_bounds__(256, 2) void k_gemm(
    const float* __restrict__ A, const float* __restrict__ coeffs,
    float* __restrict__ At)
{
    extern __shared__ __align__(16) uint32_t smu[];
    const int tid = threadIdx.x;
    const int wid = tid >> 5, lane = tid & 31;
    const int b = blockIdx.y, it0 = blockIdx.x << 7;
    const int kv = blockIdx.z;
    const int kbase = kv << 9;

    const int rb = tid >> 3;
    const int ci = (tid & 7) << 2;
    const int eb = tid >> 2;
    const int uc = (tid & 3) << 2;

    const float c0 = coeffs[0];
    const float sbv = g_s[b];
    float rloc[4];
#pragma unroll
    for (int i = 0; i < 4; ++i) rloc[i] = sbv + g_r[b*NN + it0 + rb + (i << 5)];

    const float* Ab = A  + ((size_t)b*NN + it0)*NN;
    float*       Ob = At + ((size_t)b*NN + it0)*NN;
    const uint32_t* Bhg = g_Bhi + (size_t)b*DD*(NN/2);
    const uint32_t* Blg = g_Blo + (size_t)b*DD*(NN/2);
    float*       Pb = (kv == 0 ? g_part0 : g_part1) + ((size_t)b*NN + it0)*DD;

    float acc[2][4][4];
#pragma unroll
    for (int mt = 0; mt < 2; ++mt)
#pragma unroll
        for (int nt = 0; nt < 4; ++nt)
#pragma unroll
            for (int q = 0; q < 4; ++q) acc[mt][nt][q] = 0.f;

    float4 Ar[4], rjv;
    uint4 Bh4, Bl4;
    auto fetch = [&](int s) {
        const int k0 = kbase + (s << 5);
        rjv = *reinterpret_cast<const float4*>(g_r + b*NN + k0 + ci);
#pragma unroll
        for (int i = 0; i < 4; ++i)
            Ar[i] = *reinterpret_cast<const float4*>(Ab + (size_t)(rb + (i << 5))*NN + k0 + ci);
        const int k0u = k0 >> 1;
        Bh4 = *reinterpret_cast<const uint4*>(Bhg + (size_t)eb*(NN/2) + k0u + uc);
        Bl4 = *reinterpret_cast<const uint4*>(Blg + (size_t)eb*(NN/2) + k0u + uc);
    };
    auto fill = [&](int s, int buf) {
        const int k0 = kbase + (s << 5);
        uint32_t* Ahi = smu + buf * STG_U;
        uint32_t* Alo = Ahi + 128*20;
        uint32_t* Bhi = Alo + 128*20;
        uint32_t* Blo = Bhi + 64*20;
#pragma unroll
        for (int i = 0; i < 4; ++i) {
            int row = rb + (i << 5);
            float4 atv;
            atv.x = fmaf(c0, Ar[i].x, rloc[i] + rjv.x);
            atv.y = fmaf(c0, Ar[i].y, rloc[i] + rjv.y);
            atv.z = fmaf(c0, Ar[i].z, rloc[i] + rjv.z);
            atv.w = fmaf(c0, Ar[i].w, rloc[i] + rjv.w);
            *reinterpret_cast<float4*>(Ob + (size_t)row*NN + k0 + ci) = atv;   // A_t out
            uint32_t bx = __float_as_uint(atv.x), by = __float_as_uint(atv.y);
            uint32_t bz = __float_as_uint(atv.z), bw = __float_as_uint(atv.w);
            float lx = atv.x - __uint_as_float(bx & 0xffff0000u);
            float ly = atv.y - __uint_as_float(by & 0xffff0000u);
            float lz = atv.z - __uint_as_float(bz & 0xffff0000u);
            float lw = atv.w - __uint_as_float(bw & 0xffff0000u);
            uint2 hp, lp;
            hp.x = prmt7632(bx, by); hp.y = prmt7632(bz, bw);
            lp.x = prmt7632(__float_as_uint(lx), __float_as_uint(ly));
            lp.y = prmt7632(__float_as_uint(lz), __float_as_uint(lw));
            *reinterpret_cast<uint2*>(Ahi + row*20 + (ci >> 1)) = hp;
            *reinterpret_cast<uint2*>(Alo + row*20 + (ci >> 1)) = lp;
        }
        *reinterpret_cast<uint4*>(Bhi + eb*20 + uc) = Bh4;
        *reinterpret_cast<uint4*>(Blo + eb*20 + uc) = Bl4;
    };

    const int g = lane >> 2, t = lane & 3;
    const int m0 = (wid & 3) << 5;
    const int e0 = (wid >> 2) << 5;

    fetch(0);
    fill(0, 0);
    __syncthreads();

    for (int s = 0; s < 16; ++s) {
        if (s < 15) fetch(s + 1);
        const uint32_t* Ahi = smu + (s & 1) * STG_U;
        const uint32_t* Alo = Ahi + 128*20;
        const uint32_t* Bhi = Alo + 128*20;
        const uint32_t* Blo = Bhi + 64*20;
#pragma unroll
        for (int ks = 0; ks < 2; ++ks) {
            const int kk2 = ks << 3;
            uint32_t ah[2][4], al[2][4];
#pragma unroll
            for (int mt = 0; mt < 2; ++mt) {
                const int rowb = m0 + (mt << 4);
                ah[mt][0] = Ahi[(rowb+g  )*20 + kk2 + t];
                ah[mt][1] = Ahi[(rowb+g+8)*20 + kk2 + t];
                ah[mt][2] = Ahi[(rowb+g  )*20 + kk2 + 4 + t];
                ah[mt][3] = Ahi[(rowb+g+8)*20 + kk2 + 4 + t];
                al[mt][0] = Alo[(rowb+g  )*20 + kk2 + t];
                al[mt][1] = Alo[(rowb+g+8)*20 + kk2 + t];
                al[mt][2] = Alo[(rowb+g  )*20 + kk2 + 4 + t];
                al[mt][3] = Alo[(rowb+g+8)*20 + kk2 + 4 + t];
            }
            uint32_t bh[4][2], bl[4][2];
#pragma unroll
            for (int nt = 0; nt < 4; ++nt) {
                const int er = (e0 + (nt << 3) + g)*20 + kk2 + t;
                bh[nt][0] = Bhi[er]; bh[nt][1] = Bhi[er + 4];
                bl[nt][0] = Blo[er]; bl[nt][1] = Blo[er + 4];
            }
#pragma unroll
            for (int mt = 0; mt < 2; ++mt)
#pragma unroll
                for (int nt = 0; nt < 4; ++nt)
                    mma16(acc[mt][nt], ah[mt], bh[nt][0], bh[nt][1]);
#pragma unroll
            for (int mt = 0; mt < 2; ++mt)
#pragma unroll
                for (int nt = 0; nt < 4; ++nt)
                    mma16(acc[mt][nt], ah[mt], bl[nt][0], bl[nt][1]);
#pragma unroll
            for (int mt = 0; mt < 2; ++mt)
#pragma unroll
                for (int nt = 0; nt < 4; ++nt)
                    mma16(acc[mt][nt], al[mt], bh[nt][0], bh[nt][1]);
        }
        if (s < 15) {
            fill(s + 1, (s + 1) & 1);
            __syncthreads();
        }
    }

#pragma unroll
    for (int mt = 0; mt < 2; ++mt) {
        const int row1 = m0 + (mt << 4) + g;
        const size_t b1 = (size_t)row1*DD;
        const size_t b2 = b1 + 8*DD;
#pragma unroll
        for (int nt = 0; nt < 4; ++nt) {
            const int col = e0 + (nt << 3) + (t << 1);
            float2 o1; o1.x = acc[mt][nt][0]; o1.y = acc[mt][nt][1];
            *reinterpret_cast<float2*>(Pb + b1 + col) = o1;
            float2 o2; o2.x = acc[mt][nt][2]; o2.y = acc[mt][nt][3];
            *reinterpret_cast<float2*>(Pb + b2 + col) = o2;
        }
    }
}

// ============ kernel 5: fold split-K partials into X1_t ============
__global__ __launch_bounds__(256) void k_fix(float* __restrict__ x1o) {
    const size_t i = ((size_t)blockIdx.x * 256 + threadIdx.x) << 2;
    const float inv = 1.0f / 1024.0f;
    float4 p0 = *reinterpret_cast<const float4*>(g_part0 + i);
    float4 p1 = *reinterpret_cast<const float4*>(g_part1 + i);
    float4 x  = *reinterpret_cast<const float4*>(x1o + i);
    x.x += (p0.x + p1.x) * inv;
    x.y += (p0.y + p1.y) * inv;
    x.z += (p0.z + p1.z) * inv;
    x.w += (p0.w + p1.w) * inv;
    *reinterpret_cast<float4*>(x1o + i) = x;
}

// ---------------- launch ----------------
extern "C" void kernel_launch(void* const* d_in, const int* in_sizes, int n_in,
                              void* d_out, int out_size)
{
    const float* A      = (const float*)d_in[0];
    const float* X      = (const float*)d_in[1];
    const float* coeffs = (const float*)d_in[2];
    const float* wA1    = (const float*)d_in[3];
    const float* wA2    = (const float*)d_in[4];
    const float* w11    = (const float*)d_in[5];
    const float* w12    = (const float*)d_in[6];
    const float* w13    = (const float*)d_in[7];
    const float* w14    = (const float*)d_in[8];
    const float* w15    = (const float*)d_in[9];
    const float* w16    = (const float*)d_in[10];
    const float* w21    = (const float*)d_in[11];
    const float* w22    = (const float*)d_in[12];
    const float* w23    = (const float*)d_in[13];
    const float* w24    = (const float*)d_in[14];
    const float* w25    = (const float*)d_in[15];
    const float* w26    = (const float*)d_in[16];

    float* out = (float*)d_out;
    float* x1o = out + OUT_OFF;

    const int FRONT_SMEM = (128*DD + 2*64*68) * (int)sizeof(float);  // 67584
    cudaFuncSetAttribute(k_front, cudaFuncAttributeMaxDynamicSharedMemorySize, FRONT_SMEM);
    const int GEMM_SMEM = 2 * STG_U * (int)sizeof(uint32_t);         // 61440
    cudaFuncSetAttribute(k_gemm, cudaFuncAttributeMaxDynamicSharedMemorySize, GEMM_SMEM);

    k_front       <<<2192, 256, FRONT_SMEM>>>(A, X, coeffs, wA1, w11, w21, x1o);
    k_batch_finish<<<16, 256>>>(coeffs, wA2, w12, w15, w16, w22, w25, w26);
    k_finish      <<<dim3(8,16), 256>>>(w13, w14, w23, w24, x1o);
    k_gemm        <<<dim3(8,16,2), 256, GEMM_SMEM>>>(A, coeffs, out);
    k_fix         <<<(NB*NN*DD)/(256*4), 256>>>(x1o);
}